// round 1
// baseline (speedup 1.0000x reference)
#include <cuda_runtime.h>
#include <math.h>

// MSA column global attention, fused single kernel.
// grid = L (one CTA per residue column l), block = 512 threads.
// Per block: loop over N in chunks of 128:
//   pass A: LN -> Xt (transposed smem), k/v projections into smem, accumulate sum_n(x)
//   then: q = (sum_x/512)@Wq * scaling, scores, softmax over n, o = attn@v (all in smem)
//   pass B: LN recompute -> gate = sigmoid(x@Wg+bg), out = (gate*o)@Wo + bo -> global

namespace {
constexpr int N_SEQ   = 512;
constexpr int L_RES   = 1024;
constexpr int D       = 64;
constexpr int NH      = 8;
constexpr int CHUNK   = 128;
constexpr int NCHUNK  = N_SEQ / CHUNK;
constexpr int XSTR    = CHUNK + 4;   // 132, multiple of 4 for float4-aligned rows
constexpr int NTHREADS = 512;
constexpr float LN_EPS = 1e-5f;

struct __align__(16) Smem {
    float wq[D][D];        // 16 KB
    float wg[D][D];        // 16 KB
    float wo[D][D];        // 16 KB
    float wkv[D][16];      // k cols 0-7, v cols 8-15
    float lnw[D], lnb[D], bgv[D], bov[D];
    float kbuf[N_SEQ][8];  // 16 KB
    float vbuf[N_SEQ][8];  // 16 KB
    float xsum[D];
    float qvec[D];
    float ovec[D];
    float bufA[D * XSTR];  // Xt[d][row]  (33 KB)
    float bufB[D * XSTR];  // scores [8][512] during attention / Gt[j][row] in pass B
};
} // namespace

__global__ void __launch_bounds__(NTHREADS, 1)
msa_col_global_attn_kernel(const float* __restrict__ msa,
                           const float* __restrict__ g_lnw, const float* __restrict__ g_lnb,
                           const float* __restrict__ g_wq,  const float* __restrict__ g_wk,
                           const float* __restrict__ g_wv,  const float* __restrict__ g_wg,
                           const float* __restrict__ g_bg,  const float* __restrict__ g_wo,
                           const float* __restrict__ g_bo,  float* __restrict__ out)
{
    extern __shared__ float smem_f[];
    Smem* s = reinterpret_cast<Smem*>(smem_f);
    const int tid = threadIdx.x;
    const int l   = blockIdx.x;

    // ---- preload weights ----
    for (int i = tid; i < D * D; i += NTHREADS) {
        (&s->wq[0][0])[i] = g_wq[i];
        (&s->wg[0][0])[i] = g_wg[i];
        (&s->wo[0][0])[i] = g_wo[i];
    }
    for (int i = tid; i < D * 8; i += NTHREADS) {
        int d = i >> 3, j = i & 7;
        s->wkv[d][j]     = g_wk[i];
        s->wkv[d][8 + j] = g_wv[i];
    }
    if (tid < D) {
        s->lnw[tid] = g_lnw[tid];
        s->lnb[tid] = g_lnb[tid];
        s->bgv[tid] = g_bg[tid];
        s->bov[tid] = g_bo[tid];
        s->xsum[tid] = 0.f;
    }
    __syncthreads();

    const int lr = tid >> 2;   // row within chunk (0..127), 4 threads per row
    const int lq = tid & 3;    // quarter: 16 columns each

    // LN a 128-row chunk and store transposed into bufA: Xt[c][row]
    auto ln_load = [&](int n0) {
        const float* src = msa + ((size_t)(n0 + lr) * L_RES + l) * D + lq * 16;
        float x[16];
        #pragma unroll
        for (int k = 0; k < 4; ++k) {
            float4 t = *reinterpret_cast<const float4*>(src + 4 * k);
            x[4*k+0] = t.x; x[4*k+1] = t.y; x[4*k+2] = t.z; x[4*k+3] = t.w;
        }
        float sm = 0.f, sq = 0.f;
        #pragma unroll
        for (int k = 0; k < 16; ++k) { sm += x[k]; sq += x[k] * x[k]; }
        sm += __shfl_xor_sync(0xffffffffu, sm, 1);
        sq += __shfl_xor_sync(0xffffffffu, sq, 1);
        sm += __shfl_xor_sync(0xffffffffu, sm, 2);
        sq += __shfl_xor_sync(0xffffffffu, sq, 2);
        float mu   = sm * (1.f / 64.f);
        float var  = sq * (1.f / 64.f) - mu * mu;
        float rstd = rsqrtf(var + LN_EPS);
        #pragma unroll
        for (int jj = 0; jj < 4; ++jj) {
            int kk = (jj + lq) & 3;            // rotate to reduce bank conflicts
            #pragma unroll
            for (int m = 0; m < 4; ++m) {
                int c = lq * 16 + kk * 4 + m;
                float v = (x[kk * 4 + m] - mu) * rstd * s->lnw[c] + s->lnb[c];
                s->bufA[c * XSTR + lr] = v;
            }
        }
    };

    const int rx  = tid >> 4;   // 0..31 -> 4 rows each
    const int c16 = tid & 15;   // 0..15

    // ================= pass A: k, v, sum_n(x) =================
    for (int ch = 0; ch < NCHUNK; ++ch) {
        const int n0 = ch * CHUNK;
        ln_load(n0);
        __syncthreads();

        // kv projection: [128 rows] x [16 cols]
        {
            float a0 = 0.f, a1 = 0.f, a2 = 0.f, a3 = 0.f;
            #pragma unroll 8
            for (int d = 0; d < D; ++d) {
                float4 xv = *reinterpret_cast<const float4*>(&s->bufA[d * XSTR + 4 * rx]);
                float  w  = s->wkv[d][c16];
                a0 += xv.x * w; a1 += xv.y * w; a2 += xv.z * w; a3 += xv.w * w;
            }
            float* dst = (c16 < 8) ? &s->kbuf[n0 + 4 * rx][c16]
                                   : &s->vbuf[n0 + 4 * rx][c16 - 8];
            dst[0] = a0; dst[8] = a1; dst[16] = a2; dst[24] = a3;
        }

        // accumulate xsum[d] += sum_rows Xt[d][row]  (deterministic)
        {
            int dd = tid >> 3, sub = tid & 7;
            const float* rowp = &s->bufA[dd * XSTR + sub * 16];
            float p = 0.f;
            #pragma unroll
            for (int i = 0; i < 16; ++i) p += rowp[i];
            p += __shfl_xor_sync(0xffffffffu, p, 1);
            p += __shfl_xor_sync(0xffffffffu, p, 2);
            p += __shfl_xor_sync(0xffffffffu, p, 4);
            if (sub == 0) s->xsum[dd] += p;
        }
        __syncthreads();
    }

    // q = (mean_n x) @ Wq * scaling    (linearity of mean & projection)
    if (tid < D) {
        float acc = 0.f;
        #pragma unroll 8
        for (int d = 0; d < D; ++d) acc += s->xsum[d] * s->wq[d][tid];
        s->qvec[tid] = acc * (float)(0.35355339059327373 / 512.0); // (1/sqrt(8))/N
    }
    __syncthreads();

    // ================= attention over n (in smem) =================
    // scores[h][n]
    {
        float4 k0 = *reinterpret_cast<const float4*>(&s->kbuf[tid][0]);
        float4 k1 = *reinterpret_cast<const float4*>(&s->kbuf[tid][4]);
        #pragma unroll
        for (int h = 0; h < NH; ++h) {
            const float* qf = &s->qvec[h * 8];
            float sc = qf[0]*k0.x + qf[1]*k0.y + qf[2]*k0.z + qf[3]*k0.w
                     + qf[4]*k1.x + qf[5]*k1.y + qf[6]*k1.z + qf[7]*k1.w;
            s->bufB[h * N_SEQ + tid] = sc;
        }
    }
    __syncthreads();

    // softmax over n + o[h][d] = sum_n attn * v  (one warp per head)
    {
        int w = tid >> 5, lane = tid & 31;
        if (w < NH) {
            float sv[16];
            float m = -1e30f;
            #pragma unroll
            for (int k = 0; k < 16; ++k) {
                sv[k] = s->bufB[w * N_SEQ + lane + 32 * k];
                m = fmaxf(m, sv[k]);
            }
            #pragma unroll
            for (int off = 16; off > 0; off >>= 1)
                m = fmaxf(m, __shfl_xor_sync(0xffffffffu, m, off));
            float ssum = 0.f;
            float acc[8];
            #pragma unroll
            for (int d = 0; d < 8; ++d) acc[d] = 0.f;
            #pragma unroll
            for (int k = 0; k < 16; ++k) {
                float e = __expf(sv[k] - m);
                ssum += e;
                int n = lane + 32 * k;
                float4 v0 = *reinterpret_cast<const float4*>(&s->vbuf[n][0]);
                float4 v1 = *reinterpret_cast<const float4*>(&s->vbuf[n][4]);
                acc[0] += e * v0.x; acc[1] += e * v0.y; acc[2] += e * v0.z; acc[3] += e * v0.w;
                acc[4] += e * v1.x; acc[5] += e * v1.y; acc[6] += e * v1.z; acc[7] += e * v1.w;
            }
            #pragma unroll
            for (int off = 16; off > 0; off >>= 1) {
                ssum += __shfl_xor_sync(0xffffffffu, ssum, off);
                #pragma unroll
                for (int d = 0; d < 8; ++d)
                    acc[d] += __shfl_xor_sync(0xffffffffu, acc[d], off);
            }
            if (lane == 0) {
                float inv = 1.f / ssum;
                #pragma unroll
                for (int d = 0; d < 8; ++d) s->ovec[w * 8 + d] = acc[d] * inv;
            }
        }
    }
    __syncthreads();

    // ================= pass B: gate & output =================
    const int jy = tid & 15;   // j-block (gate cols)
    for (int ch = 0; ch < NCHUNK; ++ch) {
        const int n0 = ch * CHUNK;
        ln_load(n0);
        __syncthreads();

        // GEMM1 (transposed output): Gt[j][row] = sigmoid(X@Wg + bg)[row][j] * ovec[j]
        {
            float acc[4][4];
            #pragma unroll
            for (int a = 0; a < 4; ++a)
                #pragma unroll
                for (int b = 0; b < 4; ++b) acc[a][b] = 0.f;
            #pragma unroll 8
            for (int d = 0; d < D; ++d) {
                float4 wv = *reinterpret_cast<const float4*>(&s->wg[d][4 * jy]);
                float4 xv = *reinterpret_cast<const float4*>(&s->bufA[d * XSTR + 4 * rx]);
                acc[0][0] += wv.x * xv.x; acc[0][1] += wv.x * xv.y; acc[0][2] += wv.x * xv.z; acc[0][3] += wv.x * xv.w;
                acc[1][0] += wv.y * xv.x; acc[1][1] += wv.y * xv.y; acc[1][2] += wv.y * xv.z; acc[1][3] += wv.y * xv.w;
                acc[2][0] += wv.z * xv.x; acc[2][1] += wv.z * xv.y; acc[2][2] += wv.z * xv.z; acc[2][3] += wv.z * xv.w;
                acc[3][0] += wv.w * xv.x; acc[3][1] += wv.w * xv.y; acc[3][2] += wv.w * xv.z; acc[3][3] += wv.w * xv.w;
            }
            #pragma unroll
            for (int jj = 0; jj < 4; ++jj) {
                int ji = (jj + jy) & 3;
                int c  = 4 * jy + ji;
                float bgc = s->bgv[c], oc = s->ovec[c];
                float4 g;
                g.x = oc / (1.f + __expf(-(acc[ji][0] + bgc)));
                g.y = oc / (1.f + __expf(-(acc[ji][1] + bgc)));
                g.z = oc / (1.f + __expf(-(acc[ji][2] + bgc)));
                g.w = oc / (1.f + __expf(-(acc[ji][3] + bgc)));
                *reinterpret_cast<float4*>(&s->bufB[c * XSTR + 4 * rx]) = g;
            }
        }
        __syncthreads();

        // GEMM2: out[row][c] = sum_j Gt[j][row] * Wo[j][c] + bo[c]
        {
            float acc[4][4];
            #pragma unroll
            for (int a = 0; a < 4; ++a)
                #pragma unroll
                for (int b = 0; b < 4; ++b) acc[a][b] = 0.f;
            #pragma unroll 8
            for (int j = 0; j < D; ++j) {
                float4 xv = *reinterpret_cast<const float4*>(&s->bufB[j * XSTR + 4 * rx]);
                float4 wv = *reinterpret_cast<const float4*>(&s->wo[j][4 * c16]);
                acc[0][0] += xv.x * wv.x; acc[0][1] += xv.x * wv.y; acc[0][2] += xv.x * wv.z; acc[0][3] += xv.x * wv.w;
                acc[1][0] += xv.y * wv.x; acc[1][1] += xv.y * wv.y; acc[1][2] += xv.y * wv.z; acc[1][3] += xv.y * wv.w;
                acc[2][0] += xv.z * wv.x; acc[2][1] += xv.z * wv.y; acc[2][2] += xv.z * wv.z; acc[2][3] += xv.z * wv.w;
                acc[3][0] += xv.w * wv.x; acc[3][1] += xv.w * wv.y; acc[3][2] += xv.w * wv.z; acc[3][3] += xv.w * wv.w;
            }
            float b0 = s->bov[4 * c16 + 0], b1 = s->bov[4 * c16 + 1];
            float b2 = s->bov[4 * c16 + 2], b3 = s->bov[4 * c16 + 3];
            #pragma unroll
            for (int i = 0; i < 4; ++i) {
                size_t base = ((size_t)(n0 + 4 * rx + i) * L_RES + l) * D + 4 * c16;
                float4 ov;
                ov.x = acc[i][0] + b0; ov.y = acc[i][1] + b1;
                ov.z = acc[i][2] + b2; ov.w = acc[i][3] + b3;
                *reinterpret_cast<float4*>(&out[base]) = ov;
            }
        }
        __syncthreads();
    }
}

extern "C" void kernel_launch(void* const* d_in, const int* in_sizes, int n_in,
                              void* d_out, int out_size) {
    const float* msa  = (const float*)d_in[0];
    const float* lnw  = (const float*)d_in[1];
    const float* lnb  = (const float*)d_in[2];
    const float* wq   = (const float*)d_in[3];
    const float* wk   = (const float*)d_in[4];
    const float* wv   = (const float*)d_in[5];
    const float* wg   = (const float*)d_in[6];
    const float* bg   = (const float*)d_in[7];
    const float* wo   = (const float*)d_in[8];
    const float* bo   = (const float*)d_in[9];
    float* out = (float*)d_out;

    const int smem_bytes = (int)sizeof(Smem);
    cudaFuncSetAttribute(msa_col_global_attn_kernel,
                         cudaFuncAttributeMaxDynamicSharedMemorySize, smem_bytes);
    msa_col_global_attn_kernel<<<L_RES, NTHREADS, smem_bytes>>>(
        msa, lnw, lnb, wq, wk, wv, wg, bg, wo, bo, out);
}

// round 2
// speedup vs baseline: 1.3933x; 1.3933x over previous
#include <cuda_runtime.h>
#include <math.h>

namespace {
constexpr int N_SEQ = 512;
constexpr int L_RES = 1024;
constexpr int D     = 64;
constexpr int NH    = 8;
constexpr int CHUNK = 256;
constexpr int NCHUNK = N_SEQ / CHUNK;
constexpr int XSTR  = 260;            // floats per column (256 rows + pad), mult of 4
constexpr int NT    = 512;
constexpr float LN_EPS = 1e-5f;

typedef unsigned long long ull;

struct __align__(16) Smem {
    float wq[D * D];          // 16 KB
    float wg[D * D];          // 16 KB
    float wo[D * D];          // 16 KB
    float wkv[D][16];         // 4 KB   (k cols 0-7, v cols 8-15)
    float lnw[D], lnb[D], bgv[D], bov[D];
    float kbuf[N_SEQ][8];     // 16 KB
    float vbuf[N_SEQ][8];     // 16 KB
    float xsum[D], qvec[D], ovec[D];
    float bufA[D * XSTR];     // Xt[c][row] swizzled, 65 KB
    float bufB[D * XSTR];     // scores / Gt[c][row] swizzled, 65 KB
};

__device__ __forceinline__ void ffma2(ull& d_, ull a, ull b) {
    asm("fma.rn.f32x2 %0, %1, %2, %0;" : "+l"(d_) : "l"(a), "l"(b));
}
__device__ __forceinline__ ull splat2(float x) {
    ull r; asm("mov.b64 %0, {%1, %1};" : "=l"(r) : "f"(x)); return r;
}
__device__ __forceinline__ ull add2(ull a, ull b) {
    ull r; asm("add.rn.f32x2 %0, %1, %2;" : "=l"(r) : "l"(a), "l"(b)); return r;
}
__device__ __forceinline__ void unpack2(ull u, float& lo, float& hi) {
    asm("mov.b64 {%0, %1}, %2;" : "=f"(lo), "=f"(hi) : "l"(u));
}
} // namespace

__global__ void __launch_bounds__(NT, 1)
msa_col_attn_f32x2(const float* __restrict__ msa,
                   const float* __restrict__ g_lnw, const float* __restrict__ g_lnb,
                   const float* __restrict__ g_wq,  const float* __restrict__ g_wk,
                   const float* __restrict__ g_wv,  const float* __restrict__ g_wg,
                   const float* __restrict__ g_bg,  const float* __restrict__ g_wo,
                   const float* __restrict__ g_bo,  float* __restrict__ out)
{
    extern __shared__ float smem_f[];
    Smem* s = reinterpret_cast<Smem*>(smem_f);
    const int tid = threadIdx.x;
    const int l   = blockIdx.x;

    // ---- preload weights ----
    {
        const float4* q4 = (const float4*)g_wq;
        const float4* g4 = (const float4*)g_wg;
        const float4* o4 = (const float4*)g_wo;
        #pragma unroll
        for (int i = 0; i < 2; ++i) {
            int idx = tid + i * NT;
            ((float4*)s->wq)[idx] = q4[idx];
            ((float4*)s->wg)[idx] = g4[idx];
            ((float4*)s->wo)[idx] = o4[idx];
        }
        int d = tid >> 3, j = tid & 7;
        s->wkv[d][j]     = g_wk[tid];
        s->wkv[d][8 + j] = g_wv[tid];
        if (tid < D) {
            s->lnw[tid] = g_lnw[tid];
            s->lnb[tid] = g_lnb[tid];
            s->bgv[tid] = g_bg[tid];
            s->bov[tid] = g_bo[tid];
            s->xsum[tid] = 0.f;
        }
    }
    __syncthreads();

    // LN thread map: 2 threads per row, 32 features each
    const int lrow  = tid >> 1;       // 0..255
    const int lhalf = tid & 1;        // 0/1 -> cols 32h..32h+31
    const int lrb   = lrow >> 2;      // row-block (4 rows each)
    const int lr0   = lrow & 3;

    // LN a 256-row chunk into bufA: element (c,row) at c*XSTR + 4*((row>>2)^((c>>3)&7)) + (row&3)
    auto ln_load = [&](int n0) {
        const float* src = msa + ((size_t)(n0 + lrow) * L_RES + l) * D + lhalf * 32;
        float x[32];
        #pragma unroll
        for (int k = 0; k < 8; ++k) {
            float4 t = *reinterpret_cast<const float4*>(src + 4 * k);
            x[4*k+0]=t.x; x[4*k+1]=t.y; x[4*k+2]=t.z; x[4*k+3]=t.w;
        }
        float sm = 0.f, sq = 0.f;
        #pragma unroll
        for (int k = 0; k < 32; ++k) { sm += x[k]; sq = fmaf(x[k], x[k], sq); }
        sm += __shfl_xor_sync(0xffffffffu, sm, 1);
        sq += __shfl_xor_sync(0xffffffffu, sq, 1);
        float mu   = sm * (1.f / 64.f);
        float var  = sq * (1.f / 64.f) - mu * mu;
        float rstd = rsqrtf(var + LN_EPS);
        float mrs  = -mu * rstd;
        #pragma unroll
        for (int kb = 0; kb < 4; ++kb) {
            int c0 = lhalf * 32 + kb * 8;
            int sw = (c0 >> 3) & 7;
            float* dst = &s->bufA[c0 * XSTR + 4 * (lrb ^ sw) + lr0];
            #pragma unroll
            for (int m = 0; m < 8; ++m) {
                float t = fmaf(x[kb * 8 + m], rstd, mrs);
                dst[m * XSTR] = fmaf(t, s->lnw[c0 + m], s->lnb[c0 + m]);
            }
        }
    };

    // GEMM thread map: 8 cols x 4 rows per thread
    const int cg = tid & 7;    // col group: cols 8cg..8cg+7 (or kv col-pair 2cg,2cg+1)
    const int rg = tid >> 3;   // row block: rows 4rg..4rg+3

    // ================= pass A: k, v, xsum =================
    for (int ch = 0; ch < NCHUNK; ++ch) {
        const int n0 = ch * CHUNK;
        ln_load(n0);
        __syncthreads();

        // kv projection (4 rows x 1 col-pair per thread)
        {
            ull a0 = 0, a1 = 0, a2 = 0, a3 = 0;
            #pragma unroll 4
            for (int db = 0; db < 8; ++db) {
                const float* xb = &s->bufA[(db * 8) * XSTR + 4 * (rg ^ db)];
                const float* wb = &s->wkv[db * 8][2 * cg];
                #pragma unroll
                for (int m = 0; m < 8; ++m) {
                    float4 xv = *reinterpret_cast<const float4*>(xb + m * XSTR);
                    ull w = *reinterpret_cast<const ull*>(wb + m * 16);
                    ffma2(a0, splat2(xv.x), w);
                    ffma2(a1, splat2(xv.y), w);
                    ffma2(a2, splat2(xv.z), w);
                    ffma2(a3, splat2(xv.w), w);
                }
            }
            int base = n0 + 4 * rg;
            float* dst = (cg < 4) ? &s->kbuf[base][2 * cg] : &s->vbuf[base][2 * (cg - 4)];
            *reinterpret_cast<ull*>(dst)      = a0;
            *reinterpret_cast<ull*>(dst + 8)  = a1;
            *reinterpret_cast<ull*>(dst + 16) = a2;
            *reinterpret_cast<ull*>(dst + 24) = a3;
        }

        // xsum[d] += sum over rows of column d (swizzle is a row permutation: sum invariant)
        {
            const float* colp = &s->bufA[rg * XSTR];  // rg doubles as d here (tid>>3)
            float p = 0.f;
            #pragma unroll
            for (int b = 0; b < 8; ++b) {
                float4 v = *reinterpret_cast<const float4*>(colp + 4 * (cg * 8 + b));
                p += (v.x + v.y) + (v.z + v.w);
            }
            p += __shfl_xor_sync(0xffffffffu, p, 1);
            p += __shfl_xor_sync(0xffffffffu, p, 2);
            p += __shfl_xor_sync(0xffffffffu, p, 4);
            if (cg == 0) s->xsum[rg] += p;
        }
        __syncthreads();
    }

    // q = (mean_n x) @ Wq * scaling   (mean commutes with the projection)
    if (tid < D) {
        float acc = 0.f;
        #pragma unroll 8
        for (int d = 0; d < D; ++d) acc = fmaf(s->xsum[d], s->wq[d * 64 + tid], acc);
        s->qvec[tid] = acc * (float)(0.35355339059327373 / 512.0); // (1/sqrt(8))/N
    }
    __syncthreads();

    // scores[h][n] into bufB
    {
        float4 k0 = *reinterpret_cast<const float4*>(&s->kbuf[tid][0]);
        float4 k1 = *reinterpret_cast<const float4*>(&s->kbuf[tid][4]);
        #pragma unroll
        for (int h = 0; h < NH; ++h) {
            const float* qf = &s->qvec[h * 8];
            float sc = qf[0]*k0.x + qf[1]*k0.y + qf[2]*k0.z + qf[3]*k0.w
                     + qf[4]*k1.x + qf[5]*k1.y + qf[6]*k1.z + qf[7]*k1.w;
            s->bufB[h * N_SEQ + tid] = sc;
        }
    }
    __syncthreads();

    // softmax over n + o = attn @ v  (one warp per head)
    {
        int w = tid >> 5, lane = tid & 31;
        if (w < NH) {
            float sv[16];
            float m = -1e30f;
            #pragma unroll
            for (int k = 0; k < 16; ++k) {
                sv[k] = s->bufB[w * N_SEQ + lane + 32 * k];
                m = fmaxf(m, sv[k]);
            }
            #pragma unroll
            for (int off = 16; off > 0; off >>= 1)
                m = fmaxf(m, __shfl_xor_sync(0xffffffffu, m, off));
            float ssum = 0.f;
            float acc[8];
            #pragma unroll
            for (int d = 0; d < 8; ++d) acc[d] = 0.f;
            #pragma unroll
            for (int k = 0; k < 16; ++k) {
                float e = __expf(sv[k] - m);
                ssum += e;
                int n = lane + 32 * k;
                float4 v0 = *reinterpret_cast<const float4*>(&s->vbuf[n][0]);
                float4 v1 = *reinterpret_cast<const float4*>(&s->vbuf[n][4]);
                acc[0] = fmaf(e, v0.x, acc[0]); acc[1] = fmaf(e, v0.y, acc[1]);
                acc[2] = fmaf(e, v0.z, acc[2]); acc[3] = fmaf(e, v0.w, acc[3]);
                acc[4] = fmaf(e, v1.x, acc[4]); acc[5] = fmaf(e, v1.y, acc[5]);
                acc[6] = fmaf(e, v1.z, acc[6]); acc[7] = fmaf(e, v1.w, acc[7]);
            }
            #pragma unroll
            for (int off = 16; off > 0; off >>= 1) {
                ssum += __shfl_xor_sync(0xffffffffu, ssum, off);
                #pragma unroll
                for (int d = 0; d < 8; ++d)
                    acc[d] += __shfl_xor_sync(0xffffffffu, acc[d], off);
            }
            if (lane == 0) {
                float inv = 1.f / ssum;
                #pragma unroll
                for (int d = 0; d < 8; ++d) s->ovec[w * 8 + d] = acc[d] * inv;
            }
        }
    }
    __syncthreads();

    // hoist per-thread gate/bias constants (cols 8cg..8cg+7)
    float og[8], bb[8];
    #pragma unroll
    for (int k = 0; k < 8; ++k) { og[k] = s->ovec[8 * cg + k]; bb[k] = s->bgv[8 * cg + k]; }
    ulonglong2 boA = *reinterpret_cast<const ulonglong2*>(&s->bov[8 * cg]);
    ulonglong2 boB = *reinterpret_cast<const ulonglong2*>(&s->bov[8 * cg + 4]);

    // ================= pass B: gate & output =================
    for (int ch = 0; ch < NCHUNK; ++ch) {
        const int n0 = ch * CHUNK;
        ln_load(n0);
        __syncthreads();

        // GEMM1: pre-gate = X @ Wg ; acc[row i][col-pair p], cols 8cg+2p, +1
        {
            ull acc[4][4];
            #pragma unroll
            for (int i = 0; i < 4; ++i)
                #pragma unroll
                for (int p = 0; p < 4; ++p) acc[i][p] = 0;
            #pragma unroll 4
            for (int db = 0; db < 8; ++db) {
                const float* xb = &s->bufA[(db * 8) * XSTR + 4 * (rg ^ db)];
                const float* wr = &s->wg[(db * 8) * 64 + 8 * cg];
                #pragma unroll
                for (int m = 0; m < 8; ++m) {
                    float4 xv = *reinterpret_cast<const float4*>(xb + m * XSTR);
                    ulonglong2 wA = *reinterpret_cast<const ulonglong2*>(wr + m * 64);
                    ulonglong2 wB = *reinterpret_cast<const ulonglong2*>(wr + m * 64 + 4);
                    ull s0 = splat2(xv.x), s1 = splat2(xv.y), s2 = splat2(xv.z), s3 = splat2(xv.w);
                    ffma2(acc[0][0], s0, wA.x); ffma2(acc[0][1], s0, wA.y);
                    ffma2(acc[0][2], s0, wB.x); ffma2(acc[0][3], s0, wB.y);
                    ffma2(acc[1][0], s1, wA.x); ffma2(acc[1][1], s1, wA.y);
                    ffma2(acc[1][2], s1, wB.x); ffma2(acc[1][3], s1, wB.y);
                    ffma2(acc[2][0], s2, wA.x); ffma2(acc[2][1], s2, wA.y);
                    ffma2(acc[2][2], s2, wB.x); ffma2(acc[2][3], s2, wB.y);
                    ffma2(acc[3][0], s3, wA.x); ffma2(acc[3][1], s3, wA.y);
                    ffma2(acc[3][2], s3, wB.x); ffma2(acc[3][3], s3, wB.y);
                }
            }
            // epilogue: Gt[c][row] = ovec[c] * sigmoid(v + bg[c]) into bufB (swizzled)
            #pragma unroll
            for (int k = 0; k < 8; ++k) {
                int p = k >> 1;
                float g[4];
                #pragma unroll
                for (int i = 0; i < 4; ++i) {
                    float lo, hi;
                    unpack2(acc[i][p], lo, hi);
                    float v = (k & 1) ? hi : lo;
                    float e = __expf(-(v + bb[k]));
                    g[i] = __fdividef(og[k], 1.f + e);
                }
                float4 st = make_float4(g[0], g[1], g[2], g[3]);
                *reinterpret_cast<float4*>(&s->bufB[(8 * cg + k) * XSTR + 4 * (rg ^ cg)]) = st;
            }
        }
        __syncthreads();

        // GEMM2: out = G @ Wo + bo
        {
            ull acc[4][4];
            #pragma unroll
            for (int i = 0; i < 4; ++i)
                #pragma unroll
                for (int p = 0; p < 4; ++p) acc[i][p] = 0;
            #pragma unroll 4
            for (int db = 0; db < 8; ++db) {
                const float* gb = &s->bufB[(db * 8) * XSTR + 4 * (rg ^ db)];
                const float* wr = &s->wo[(db * 8) * 64 + 8 * cg];
                #pragma unroll
                for (int m = 0; m < 8; ++m) {
                    float4 gv = *reinterpret_cast<const float4*>(gb + m * XSTR);
                    ulonglong2 wA = *reinterpret_cast<const ulonglong2*>(wr + m * 64);
                    ulonglong2 wB = *reinterpret_cast<const ulonglong2*>(wr + m * 64 + 4);
                    ull s0 = splat2(gv.x), s1 = splat2(gv.y), s2 = splat2(gv.z), s3 = splat2(gv.w);
                    ffma2(acc[0][0], s0, wA.x); ffma2(acc[0][1], s0, wA.y);
                    ffma2(acc[0][2], s0, wB.x); ffma2(acc[0][3], s0, wB.y);
                    ffma2(acc[1][0], s1, wA.x); ffma2(acc[1][1], s1, wA.y);
                    ffma2(acc[1][2], s1, wB.x); ffma2(acc[1][3], s1, wB.y);
                    ffma2(acc[2][0], s2, wA.x); ffma2(acc[2][1], s2, wA.y);
                    ffma2(acc[2][2], s2, wB.x); ffma2(acc[2][3], s2, wB.y);
                    ffma2(acc[3][0], s3, wA.x); ffma2(acc[3][1], s3, wA.y);
                    ffma2(acc[3][2], s3, wB.x); ffma2(acc[3][3], s3, wB.y);
                }
            }
            #pragma unroll
            for (int i = 0; i < 4; ++i) {
                size_t r = (size_t)(n0 + 4 * rg + i);
                float* op = out + (r * L_RES + l) * D + 8 * cg;
                ulonglong2 v0, v1;
                v0.x = add2(acc[i][0], boA.x); v0.y = add2(acc[i][1], boA.y);
                v1.x = add2(acc[i][2], boB.x); v1.y = add2(acc[i][3], boB.y);
                *reinterpret_cast<ulonglong2*>(op)     = v0;
                *reinterpret_cast<ulonglong2*>(op + 4) = v1;
            }
        }
        __syncthreads();
    }
}

extern "C" void kernel_launch(void* const* d_in, const int* in_sizes, int n_in,
                              void* d_out, int out_size) {
    const float* msa = (const float*)d_in[0];
    const float* lnw = (const float*)d_in[1];
    const float* lnb = (const float*)d_in[2];
    const float* wq  = (const float*)d_in[3];
    const float* wk  = (const float*)d_in[4];
    const float* wv  = (const float*)d_in[5];
    const float* wg  = (const float*)d_in[6];
    const float* bg  = (const float*)d_in[7];
    const float* wo  = (const float*)d_in[8];
    const float* bo  = (const float*)d_in[9];
    float* out = (float*)d_out;

    const int smem_bytes = (int)sizeof(Smem);
    cudaFuncSetAttribute(msa_col_attn_f32x2,
                         cudaFuncAttributeMaxDynamicSharedMemorySize, smem_bytes);
    msa_col_attn_f32x2<<<L_RES, NT, smem_bytes>>>(
        msa, lnw, lnb, wq, wk, wv, wg, bg, wo, bo, out);
}

// round 3
// speedup vs baseline: 2.2780x; 1.6350x over previous
#include <cuda_runtime.h>
#include <cuda_bf16.h>
#include <math.h>

namespace {
constexpr int NSEQ = 512;
constexpr int LRES = 1024;
constexpr int D    = 64;
constexpr int NH   = 8;
constexpr int CH   = 128;    // rows per pass-A chunk
constexpr int NCH  = 4;
constexpr int NT   = 512;
constexpr float LN_EPS = 1e-5f;

typedef unsigned long long ull;

struct __align__(16) Smem {
    float wg[64 * 64];            // 16 KB
    float wo[64 * 64];            // 16 KB (scaled by ovec before GEMM2)
    float wkv[64][16];            // 4 KB  (k cols 0-7, v cols 8-15)
    float lnw[64], lnb[64], bgv[64], bov[64], xsum[64], qvec[64], ovec[64];
    float xpart[16][64];          // per-warp xsum partials / later qvec partials
    __nv_bfloat16 kbufh[NSEQ][8]; // 8 KB
    float vbuf[NSEQ][8];          // 16 KB
    float bufA[64 * CH];          // 32 KB: X transposed+swizzled; later scores[8][512]
    float gc[64 * NSEQ];          // 128 KB: gate cache, transposed+swizzled
};

__device__ __forceinline__ int swz(int c) { return ((c >> 3) ^ c) & 7; }
__device__ __forceinline__ void ffma2(ull& d_, ull a, ull b) {
    asm("fma.rn.f32x2 %0, %1, %2, %0;" : "+l"(d_) : "l"(a), "l"(b));
}
__device__ __forceinline__ ull splat2(float x) {
    ull r; asm("mov.b64 %0, {%1, %1};" : "=l"(r) : "f"(x)); return r;
}
__device__ __forceinline__ ull add2(ull a, ull b) {
    ull r; asm("add.rn.f32x2 %0, %1, %2;" : "=l"(r) : "l"(a), "l"(b)); return r;
}
__device__ __forceinline__ void unpack2(ull u, float& lo, float& hi) {
    asm("mov.b64 {%0, %1}, %2;" : "=f"(lo), "=f"(hi) : "l"(u));
}
__device__ __forceinline__ float sigmoid_fast(float v) {
    return __fdividef(1.f, 1.f + __expf(-v));
}
} // namespace

__global__ void __launch_bounds__(NT, 1)
msa_col_attn_v3(const float* __restrict__ msa,
                const float* __restrict__ g_lnw, const float* __restrict__ g_lnb,
                const float* __restrict__ g_wq,  const float* __restrict__ g_wk,
                const float* __restrict__ g_wv,  const float* __restrict__ g_wg,
                const float* __restrict__ g_bg,  const float* __restrict__ g_wo,
                const float* __restrict__ g_bo,  float* __restrict__ out)
{
    extern __shared__ float smem_f[];
    Smem* s = reinterpret_cast<Smem*>(smem_f);
    const int tid  = threadIdx.x;
    const int l    = blockIdx.x;
    const int lane = tid & 31;

    // ---- preamble loads ----
    #pragma unroll
    for (int i = 0; i < 2; ++i) {
        int idx = tid + i * NT;
        ((float4*)s->wg)[idx] = ((const float4*)g_wg)[idx];
        ((float4*)s->wo)[idx] = ((const float4*)g_wo)[idx];
    }
    {
        int d = tid >> 3, j = tid & 7;
        s->wkv[d][j]     = g_wk[tid];
        s->wkv[d][8 + j] = g_wv[tid];
    }
    if (tid < 64) {
        s->lnw[tid] = g_lnw[tid];
        s->lnb[tid] = g_lnb[tid];
        s->bgv[tid] = g_bg[tid];
        s->bov[tid] = g_bo[tid];
    }
    #pragma unroll
    for (int i = 0; i < 2; ++i) (&s->xpart[0][0])[tid + i * NT] = 0.f;

    // wq held in registers: thread (dg = tid>>6, c = tid&63) holds wq[8dg+i][c]
    float wqr[8];
    {
        int dg = tid >> 6, c = tid & 63;
        #pragma unroll
        for (int i = 0; i < 8; ++i) wqr[i] = g_wq[(8 * dg + i) * 64 + c];
    }
    __syncthreads();

    // LN map: 4 threads per row, 16 features each
    const int lrow = tid >> 2;     // 0..127
    const int lq   = tid & 3;
    // GEMM map (pass A): 4 rows x {1 kv col | 4 gate cols} per thread
    const int rgg  = tid >> 4;     // 0..31
    const int cidx = tid & 15;

    float4 pf0, pf1, pf2, pf3;     // prefetched raw row data
    {
        const float* src = msa + ((size_t)lrow * LRES + l) * D + lq * 16;
        pf0 = ((const float4*)src)[0]; pf1 = ((const float4*)src)[1];
        pf2 = ((const float4*)src)[2]; pf3 = ((const float4*)src)[3];
    }

    // ================= pass A =================
    #pragma unroll 1
    for (int ch = 0; ch < NCH; ++ch) {
        const int n0 = ch * CH;

        // prefetch next chunk (overlaps LN + GEMM below)
        float4 q0, q1, q2, q3;
        if (ch < NCH - 1) {
            const float* src = msa + ((size_t)(n0 + CH + lrow) * LRES + l) * D + lq * 16;
            q0 = ((const float4*)src)[0]; q1 = ((const float4*)src)[1];
            q2 = ((const float4*)src)[2]; q3 = ((const float4*)src)[3];
        }

        // ---- LayerNorm from registers -> bufA (transposed, swizzled) ----
        {
            float x[16];
            x[0]=pf0.x; x[1]=pf0.y; x[2]=pf0.z;  x[3]=pf0.w;
            x[4]=pf1.x; x[5]=pf1.y; x[6]=pf1.z;  x[7]=pf1.w;
            x[8]=pf2.x; x[9]=pf2.y; x[10]=pf2.z; x[11]=pf2.w;
            x[12]=pf3.x;x[13]=pf3.y;x[14]=pf3.z; x[15]=pf3.w;
            float sm = 0.f, sq = 0.f;
            #pragma unroll
            for (int k = 0; k < 16; ++k) { sm += x[k]; sq = fmaf(x[k], x[k], sq); }
            sm += __shfl_xor_sync(0xffffffffu, sm, 1);
            sq += __shfl_xor_sync(0xffffffffu, sq, 1);
            sm += __shfl_xor_sync(0xffffffffu, sm, 2);
            sq += __shfl_xor_sync(0xffffffffu, sq, 2);
            float mu   = sm * (1.f / 64.f);
            float var  = sq * (1.f / 64.f) - mu * mu;
            float rstd = rsqrtf(var + LN_EPS);
            float mrs  = -mu * rstd;
            int rb = lrow >> 2, r0 = lrow & 3;
            float xr[16];
            #pragma unroll
            for (int j = 0; j < 16; ++j) {
                int c = lq * 16 + j;
                float t = fmaf(x[j], rstd, mrs);
                float v = fmaf(t, s->lnw[c], s->lnb[c]);
                xr[j] = v;
                s->bufA[c * CH + 4 * (rb ^ swz(c)) + r0] = v;
            }
            // column-sum partials (8 rows of this warp) -> xpart[warp][c]
            #pragma unroll
            for (int j = 0; j < 16; ++j) {
                float v = xr[j];
                v += __shfl_xor_sync(0xffffffffu, v, 4);
                v += __shfl_xor_sync(0xffffffffu, v, 8);
                v += __shfl_xor_sync(0xffffffffu, v, 16);
                xr[j] = v;
            }
            if ((lane >> 2) == 0) {
                int w = tid >> 5;
                #pragma unroll
                for (int j = 0; j < 16; ++j)
                    s->xpart[w][lq * 16 + j] += xr[j];
            }
        }
        __syncthreads();

        // ---- fused kv projection + gate GEMM (reads bufA) ----
        {
            float kva0 = 0.f, kva1 = 0.f, kva2 = 0.f, kva3 = 0.f;
            ull ga[4][2] = {{0,0},{0,0},{0,0},{0,0}};
            #pragma unroll 8
            for (int d = 0; d < 64; ++d) {
                const float4 xq = *reinterpret_cast<const float4*>(
                    &s->bufA[d * CH + 4 * (rgg ^ swz(d))]);
                const float wk1 = s->wkv[d][cidx];
                kva0 = fmaf(xq.x, wk1, kva0);
                kva1 = fmaf(xq.y, wk1, kva1);
                kva2 = fmaf(xq.z, wk1, kva2);
                kva3 = fmaf(xq.w, wk1, kva3);
                const ulonglong2 w2 = *reinterpret_cast<const ulonglong2*>(
                    &s->wg[d * 64 + 4 * cidx]);
                ull s0 = splat2(xq.x), s1 = splat2(xq.y);
                ull s2 = splat2(xq.z), s3 = splat2(xq.w);
                ffma2(ga[0][0], s0, w2.x); ffma2(ga[0][1], s0, w2.y);
                ffma2(ga[1][0], s1, w2.x); ffma2(ga[1][1], s1, w2.y);
                ffma2(ga[2][0], s2, w2.x); ffma2(ga[2][1], s2, w2.y);
                ffma2(ga[3][0], s3, w2.x); ffma2(ga[3][1], s3, w2.y);
            }
            const int nr = n0 + 4 * rgg;
            if (cidx < 8) {
                s->kbufh[nr + 0][cidx] = __float2bfloat16(kva0);
                s->kbufh[nr + 1][cidx] = __float2bfloat16(kva1);
                s->kbufh[nr + 2][cidx] = __float2bfloat16(kva2);
                s->kbufh[nr + 3][cidx] = __float2bfloat16(kva3);
            } else {
                s->vbuf[nr + 0][cidx - 8] = kva0;
                s->vbuf[nr + 1][cidx - 8] = kva1;
                s->vbuf[nr + 2][cidx - 8] = kva2;
                s->vbuf[nr + 3][cidx - 8] = kva3;
            }
            // gate epilogue: sigmoid(v + bg) -> gc (no ovec yet)
            #pragma unroll
            for (int k = 0; k < 4; ++k) {
                int c = 4 * cidx + k;
                float bgc = s->bgv[c];
                float lo, hi, v, g0, g1, g2, g3;
                unpack2(ga[0][k >> 1], lo, hi); v = (k & 1) ? hi : lo; g0 = sigmoid_fast(v + bgc);
                unpack2(ga[1][k >> 1], lo, hi); v = (k & 1) ? hi : lo; g1 = sigmoid_fast(v + bgc);
                unpack2(ga[2][k >> 1], lo, hi); v = (k & 1) ? hi : lo; g2 = sigmoid_fast(v + bgc);
                unpack2(ga[3][k >> 1], lo, hi); v = (k & 1) ? hi : lo; g3 = sigmoid_fast(v + bgc);
                *reinterpret_cast<float4*>(&s->gc[c * NSEQ + n0 + 4 * (rgg ^ swz(c))]) =
                    make_float4(g0, g1, g2, g3);
            }
        }
        __syncthreads();
        pf0 = q0; pf1 = q1; pf2 = q2; pf3 = q3;
    }

    // ---- xsum reduce ----
    if (tid < 64) {
        float t = 0.f;
        #pragma unroll
        for (int w = 0; w < 16; ++w) t += s->xpart[w][tid];
        s->xsum[tid] = t;
    }
    __syncthreads();

    // ---- qvec = (sum_n x) @ Wq * scaling/N  (wq from registers) ----
    {
        int dg = tid >> 6, c = tid & 63;
        float p = 0.f;
        #pragma unroll
        for (int i = 0; i < 8; ++i) p = fmaf(s->xsum[8 * dg + i], wqr[i], p);
        s->xpart[dg][c] = p;   // reuse xpart rows 0-7 as qvec partials
    }
    __syncthreads();
    if (tid < 64) {
        float q = 0.f;
        #pragma unroll
        for (int dg = 0; dg < 8; ++dg) q += s->xpart[dg][tid];
        s->qvec[tid] = q * (float)(0.35355339059327373 / 512.0);
    }
    __syncthreads();

    // ---- scores[h][n] into bufA (free now) ----
    float* scores = s->bufA;
    {
        const __nv_bfloat162* kp = reinterpret_cast<const __nv_bfloat162*>(&s->kbufh[tid][0]);
        float2 p0 = __bfloat1622float2(kp[0]);
        float2 p1 = __bfloat1622float2(kp[1]);
        float2 p2 = __bfloat1622float2(kp[2]);
        float2 p3 = __bfloat1622float2(kp[3]);
        #pragma unroll
        for (int h = 0; h < NH; ++h) {
            const float* qf = &s->qvec[h * 8];
            float sc = qf[0]*p0.x + qf[1]*p0.y + qf[2]*p1.x + qf[3]*p1.y
                     + qf[4]*p2.x + qf[5]*p2.y + qf[6]*p3.x + qf[7]*p3.y;
            scores[h * NSEQ + tid] = sc;
        }
    }
    __syncthreads();

    // ---- softmax + o = attn @ v  (one warp per head) ----
    {
        int w = tid >> 5;
        if (w < NH) {
            float sv[16];
            float m = -1e30f;
            #pragma unroll
            for (int k = 0; k < 16; ++k) {
                sv[k] = scores[w * NSEQ + lane + 32 * k];
                m = fmaxf(m, sv[k]);
            }
            #pragma unroll
            for (int off = 16; off > 0; off >>= 1)
                m = fmaxf(m, __shfl_xor_sync(0xffffffffu, m, off));
            float ssum = 0.f;
            float acc[8];
            #pragma unroll
            for (int d = 0; d < 8; ++d) acc[d] = 0.f;
            #pragma unroll
            for (int k = 0; k < 16; ++k) {
                float e = __expf(sv[k] - m);
                ssum += e;
                int n = lane + 32 * k;
                float4 v0 = *reinterpret_cast<const float4*>(&s->vbuf[n][0]);
                float4 v1 = *reinterpret_cast<const float4*>(&s->vbuf[n][4]);
                acc[0] = fmaf(e, v0.x, acc[0]); acc[1] = fmaf(e, v0.y, acc[1]);
                acc[2] = fmaf(e, v0.z, acc[2]); acc[3] = fmaf(e, v0.w, acc[3]);
                acc[4] = fmaf(e, v1.x, acc[4]); acc[5] = fmaf(e, v1.y, acc[5]);
                acc[6] = fmaf(e, v1.z, acc[6]); acc[7] = fmaf(e, v1.w, acc[7]);
            }
            #pragma unroll
            for (int off = 16; off > 0; off >>= 1) {
                ssum += __shfl_xor_sync(0xffffffffu, ssum, off);
                #pragma unroll
                for (int d = 0; d < 8; ++d)
                    acc[d] += __shfl_xor_sync(0xffffffffu, acc[d], off);
            }
            if (lane == 0) {
                float inv = 1.f / ssum;
                #pragma unroll
                for (int d = 0; d < 8; ++d) s->ovec[w * 8 + d] = acc[d] * inv;
            }
        }
    }
    __syncthreads();

    // ---- fold ovec into Wo rows ----
    #pragma unroll
    for (int i = 0; i < 8; ++i) {
        int idx = tid + i * NT;
        s->wo[idx] *= s->ovec[idx >> 6];
    }
    __syncthreads();

    // ================= pass B: out = G @ Wo' + bo (pure SMEM GEMM) =================
    {
        const int rg2 = tid >> 3;   // 0..63 -> rows 8rg2..8rg2+7
        const int cg  = tid & 7;    // cols 8cg..8cg+7
        ull acc[8][4];
        #pragma unroll
        for (int i = 0; i < 8; ++i)
            #pragma unroll
            for (int p = 0; p < 4; ++p) acc[i][p] = 0;

        #pragma unroll 4
        for (int d = 0; d < 64; ++d) {
            const ulonglong2 wA = *reinterpret_cast<const ulonglong2*>(&s->wo[d * 64 + 8 * cg]);
            const ulonglong2 wB = *reinterpret_cast<const ulonglong2*>(&s->wo[d * 64 + 8 * cg + 4]);
            const float4 xa = *reinterpret_cast<const float4*>(
                &s->gc[d * NSEQ + 4 * ((2 * rg2) ^ swz(d))]);
            const float4 xb = *reinterpret_cast<const float4*>(
                &s->gc[d * NSEQ + 4 * ((2 * rg2 + 1) ^ swz(d))]);
            ull t;
            t = splat2(xa.x); ffma2(acc[0][0],t,wA.x); ffma2(acc[0][1],t,wA.y); ffma2(acc[0][2],t,wB.x); ffma2(acc[0][3],t,wB.y);
            t = splat2(xa.y); ffma2(acc[1][0],t,wA.x); ffma2(acc[1][1],t,wA.y); ffma2(acc[1][2],t,wB.x); ffma2(acc[1][3],t,wB.y);
            t = splat2(xa.z); ffma2(acc[2][0],t,wA.x); ffma2(acc[2][1],t,wA.y); ffma2(acc[2][2],t,wB.x); ffma2(acc[2][3],t,wB.y);
            t = splat2(xa.w); ffma2(acc[3][0],t,wA.x); ffma2(acc[3][1],t,wA.y); ffma2(acc[3][2],t,wB.x); ffma2(acc[3][3],t,wB.y);
            t = splat2(xb.x); ffma2(acc[4][0],t,wA.x); ffma2(acc[4][1],t,wA.y); ffma2(acc[4][2],t,wB.x); ffma2(acc[4][3],t,wB.y);
            t = splat2(xb.y); ffma2(acc[5][0],t,wA.x); ffma2(acc[5][1],t,wA.y); ffma2(acc[5][2],t,wB.x); ffma2(acc[5][3],t,wB.y);
            t = splat2(xb.z); ffma2(acc[6][0],t,wA.x); ffma2(acc[6][1],t,wA.y); ffma2(acc[6][2],t,wB.x); ffma2(acc[6][3],t,wB.y);
            t = splat2(xb.w); ffma2(acc[7][0],t,wA.x); ffma2(acc[7][1],t,wA.y); ffma2(acc[7][2],t,wB.x); ffma2(acc[7][3],t,wB.y);
        }

        const ulonglong2 boA = *reinterpret_cast<const ulonglong2*>(&s->bov[8 * cg]);
        const ulonglong2 boB = *reinterpret_cast<const ulonglong2*>(&s->bov[8 * cg + 4]);
        #pragma unroll
        for (int i = 0; i < 8; ++i) {
            size_t row = (size_t)(8 * rg2 + i);
            float* op = out + (row * LRES + l) * D + 8 * cg;
            ulonglong2 v0, v1;
            v0.x = add2(acc[i][0], boA.x); v0.y = add2(acc[i][1], boA.y);
            v1.x = add2(acc[i][2], boB.x); v1.y = add2(acc[i][3], boB.y);
            *reinterpret_cast<ulonglong2*>(op)     = v0;
            *reinterpret_cast<ulonglong2*>(op + 4) = v1;
        }
    }
}

extern "C" void kernel_launch(void* const* d_in, const int* in_sizes, int n_in,
                              void* d_out, int out_size) {
    const float* msa = (const float*)d_in[0];
    const float* lnw = (const float*)d_in[1];
    const float* lnb = (const float*)d_in[2];
    const float* wq  = (const float*)d_in[3];
    const float* wk  = (const float*)d_in[4];
    const float* wv  = (const float*)d_in[5];
    const float* wg  = (const float*)d_in[6];
    const float* bg  = (const float*)d_in[7];
    const float* wo  = (const float*)d_in[8];
    const float* bo  = (const float*)d_in[9];
    float* out = (float*)d_out;

    const int smem_bytes = (int)sizeof(Smem);
    cudaFuncSetAttribute(msa_col_attn_v3,
                         cudaFuncAttributeMaxDynamicSharedMemorySize, smem_bytes);
    msa_col_attn_v3<<<LRES, NT, smem_bytes>>>(
        msa, lnw, lnb, wq, wk, wv, wg, bg, wo, bo, out);
}

// round 5
// speedup vs baseline: 2.3282x; 1.0220x over previous
#include <cuda_runtime.h>
#include <math.h>

namespace {
constexpr int NSEQ = 512;
constexpr int LRES = 1024;
constexpr int NT   = 512;
constexpr float LN_EPS = 1e-5f;

typedef unsigned long long ull;

struct __align__(16) Smem {
    float xg[64 * NSEQ];       // 128 KB: X transposed+swizzled, then G in place
    float wc[64][80];          // 20 KB: cols 0-63 Wg, 64-71 Wk, 72-79 Wv
    float wo[64 * 64];         // 16 KB (scaled by ovec before pass B)
    float kbuf[NSEQ][8];       // 16 KB
    float vT[8 * NSEQ];        // 16 KB (v transposed)
    float scores[8 * NSEQ];    // 16 KB
    float lnw[64], lnb[64], bgv[64], bov[64], xsum[64], qvec[64], ovec[64];
    float xpart[16][64];       // 4 KB
};

__device__ __forceinline__ int swz(int c) { return ((c >> 3) ^ c) & 7; }
__device__ __forceinline__ void ffma2(ull& d_, ull a, ull b) {
    asm("fma.rn.f32x2 %0, %1, %2, %0;" : "+l"(d_) : "l"(a), "l"(b));
}
__device__ __forceinline__ ull splat2(float x) {
    ull r; asm("mov.b64 %0, {%1, %1};" : "=l"(r) : "f"(x)); return r;
}
__device__ __forceinline__ ull add2(ull a, ull b) {
    ull r; asm("add.rn.f32x2 %0, %1, %2;" : "=l"(r) : "l"(a), "l"(b)); return r;
}
__device__ __forceinline__ void unpack2(ull u, float& lo, float& hi) {
    asm("mov.b64 {%0, %1}, %2;" : "=f"(lo), "=f"(hi) : "l"(u));
}
__device__ __forceinline__ float sigmoid_fast(float v) {
    return __fdividef(1.f, 1.f + __expf(-v));
}
} // namespace

__global__ void __launch_bounds__(NT, 1)
msa_col_attn_v5(const float* __restrict__ msa,
                const float* __restrict__ g_lnw, const float* __restrict__ g_lnb,
                const float* __restrict__ g_wq,  const float* __restrict__ g_wk,
                const float* __restrict__ g_wv,  const float* __restrict__ g_wg,
                const float* __restrict__ g_bg,  const float* __restrict__ g_wo,
                const float* __restrict__ g_bo,  float* __restrict__ out)
{
    extern __shared__ float smem_f[];
    Smem* s = reinterpret_cast<Smem*>(smem_f);
    const int tid  = threadIdx.x;
    const int l    = blockIdx.x;
    const int lane = tid & 31;
    const int wid  = tid >> 5;

    // ---------------- preamble: weights to SMEM ----------------
    #pragma unroll
    for (int i = 0; i < 8; ++i) {
        int idx = tid + i * NT;
        s->wc[idx >> 6][idx & 63] = g_wg[idx];
    }
    {   // Wk/Wv are exactly 512 elements each: ONE pass of 512 threads
        int d = tid >> 3, j = tid & 7;
        s->wc[d][64 + j] = g_wk[tid];
        s->wc[d][72 + j] = g_wv[tid];
    }
    #pragma unroll
    for (int i = 0; i < 2; ++i) {
        int idx = tid + i * NT;
        ((float4*)s->wo)[idx] = ((const float4*)g_wo)[idx];
    }
    if (tid < 64) {
        s->lnw[tid] = g_lnw[tid];
        s->lnb[tid] = g_lnb[tid];
        s->bgv[tid] = g_bg[tid];
        s->bov[tid] = g_bo[tid];
    }
    // wq in registers: thread (dg=tid>>6, c=tid&63) holds wq[8dg+i][c]
    float wqr[8];
    {
        int dg = tid >> 6, c = tid & 63;
        #pragma unroll
        for (int i = 0; i < 8; ++i) wqr[i] = g_wq[(8 * dg + i) * 64 + c];
    }
    __syncthreads();

    // ---------------- LayerNorm: full 512x64 -> xg (transposed, swizzled) ----------------
    // warp covers 2 rows per iteration; 16 lanes span one full 256B row
    {
        const int lq4 = lane & 15;   // 16B chunk of the row
        const int lh  = lane >> 4;   // which of the warp's 2 rows
        const size_t step = (size_t)32 * LRES * 64;
        const float* base = msa + ((size_t)(wid * 2 + lh) * LRES + l) * 64 + lq4 * 4;
        float xacc0 = 0.f, xacc1 = 0.f, xacc2 = 0.f, xacc3 = 0.f;
        float4 cur = *reinterpret_cast<const float4*>(base);
        #pragma unroll 1
        for (int it = 0; it < 16; ++it) {
            float4 nxt = make_float4(0.f, 0.f, 0.f, 0.f);
            if (it < 15)
                nxt = *reinterpret_cast<const float4*>(base + (size_t)(it + 1) * step);
            float sm = (cur.x + cur.y) + (cur.z + cur.w);
            float sq = fmaf(cur.x, cur.x, fmaf(cur.y, cur.y,
                       fmaf(cur.z, cur.z, cur.w * cur.w)));
            #pragma unroll
            for (int off = 1; off < 16; off <<= 1) {
                sm += __shfl_xor_sync(0xffffffffu, sm, off);
                sq += __shfl_xor_sync(0xffffffffu, sq, off);
            }
            float mu   = sm * (1.f / 64.f);
            float var  = sq * (1.f / 64.f) - mu * mu;
            float rstd = rsqrtf(var + LN_EPS);
            float mrs  = -mu * rstd;
            int row = it * 32 + wid * 2 + lh;
            int rb = row >> 2, r0 = row & 3;
            int c0 = 4 * lq4;
            float v0 = fmaf(fmaf(cur.x, rstd, mrs), s->lnw[c0 + 0], s->lnb[c0 + 0]);
            float v1 = fmaf(fmaf(cur.y, rstd, mrs), s->lnw[c0 + 1], s->lnb[c0 + 1]);
            float v2 = fmaf(fmaf(cur.z, rstd, mrs), s->lnw[c0 + 2], s->lnb[c0 + 2]);
            float v3 = fmaf(fmaf(cur.w, rstd, mrs), s->lnw[c0 + 3], s->lnb[c0 + 3]);
            s->xg[(c0 + 0) * NSEQ + 4 * (rb ^ swz(c0 + 0)) + r0] = v0;
            s->xg[(c0 + 1) * NSEQ + 4 * (rb ^ swz(c0 + 1)) + r0] = v1;
            s->xg[(c0 + 2) * NSEQ + 4 * (rb ^ swz(c0 + 2)) + r0] = v2;
            s->xg[(c0 + 3) * NSEQ + 4 * (rb ^ swz(c0 + 3)) + r0] = v3;
            xacc0 += v0; xacc1 += v1; xacc2 += v2; xacc3 += v3;
            cur = nxt;
        }
        xacc0 += __shfl_xor_sync(0xffffffffu, xacc0, 16);
        xacc1 += __shfl_xor_sync(0xffffffffu, xacc1, 16);
        xacc2 += __shfl_xor_sync(0xffffffffu, xacc2, 16);
        xacc3 += __shfl_xor_sync(0xffffffffu, xacc3, 16);
        if (lane < 16) {
            s->xpart[wid][4 * lq4 + 0] = xacc0;
            s->xpart[wid][4 * lq4 + 1] = xacc1;
            s->xpart[wid][4 * lq4 + 2] = xacc2;
            s->xpart[wid][4 * lq4 + 3] = xacc3;
        }
    }
    __syncthreads();

    // xsum (consumed after the next barrier)
    if (tid < 64) {
        float t = 0.f;
        #pragma unroll
        for (int w = 0; w < 16; ++w) t += s->xpart[w][tid];
        s->xsum[tid] = t;
    }

    // ---------------- pass A: gate GEMM (8 rows x 8 cols per thread) ----------------
    const int rg = tid >> 3;   // rows 8rg..8rg+7
    const int cg = tid & 7;    // gate cols 8cg..8cg+7
    ull ga[8][4];
    #pragma unroll
    for (int r = 0; r < 8; ++r)
        #pragma unroll
        for (int p = 0; p < 4; ++p) ga[r][p] = 0;

    #pragma unroll 4
    for (int d = 0; d < 64; ++d) {
        const float* xp = &s->xg[d * NSEQ];
        float4 xa = *reinterpret_cast<const float4*>(xp + 4 * ((2 * rg) ^ swz(d)));
        float4 xb = *reinterpret_cast<const float4*>(xp + 4 * ((2 * rg + 1) ^ swz(d)));
        ulonglong2 w0 = *reinterpret_cast<const ulonglong2*>(&s->wc[d][8 * cg]);
        ulonglong2 w1 = *reinterpret_cast<const ulonglong2*>(&s->wc[d][8 * cg + 4]);
        ull t;
        t = splat2(xa.x); ffma2(ga[0][0],t,w0.x); ffma2(ga[0][1],t,w0.y); ffma2(ga[0][2],t,w1.x); ffma2(ga[0][3],t,w1.y);
        t = splat2(xa.y); ffma2(ga[1][0],t,w0.x); ffma2(ga[1][1],t,w0.y); ffma2(ga[1][2],t,w1.x); ffma2(ga[1][3],t,w1.y);
        t = splat2(xa.z); ffma2(ga[2][0],t,w0.x); ffma2(ga[2][1],t,w0.y); ffma2(ga[2][2],t,w1.x); ffma2(ga[2][3],t,w1.y);
        t = splat2(xa.w); ffma2(ga[3][0],t,w0.x); ffma2(ga[3][1],t,w0.y); ffma2(ga[3][2],t,w1.x); ffma2(ga[3][3],t,w1.y);
        t = splat2(xb.x); ffma2(ga[4][0],t,w0.x); ffma2(ga[4][1],t,w0.y); ffma2(ga[4][2],t,w1.x); ffma2(ga[4][3],t,w1.y);
        t = splat2(xb.y); ffma2(ga[5][0],t,w0.x); ffma2(ga[5][1],t,w0.y); ffma2(ga[5][2],t,w1.x); ffma2(ga[5][3],t,w1.y);
        t = splat2(xb.z); ffma2(ga[6][0],t,w0.x); ffma2(ga[6][1],t,w0.y); ffma2(ga[6][2],t,w1.x); ffma2(ga[6][3],t,w1.y);
        t = splat2(xb.w); ffma2(ga[7][0],t,w0.x); ffma2(ga[7][1],t,w0.y); ffma2(ga[7][2],t,w1.x); ffma2(ga[7][3],t,w1.y);
    }

    // ---------------- pass A: kv GEMM (8 rows x 2 cols, row-pair packed) ----------------
    // cg<4 -> k cols {2cg, 2cg+1}; cg>=4 -> v cols {2cg-8, 2cg-7}
    ull ka[4][2];
    #pragma unroll
    for (int p = 0; p < 4; ++p) { ka[p][0] = 0; ka[p][1] = 0; }
    #pragma unroll 8
    for (int d = 0; d < 64; ++d) {
        const float* xp = &s->xg[d * NSEQ];
        ulonglong2 xa = *reinterpret_cast<const ulonglong2*>(xp + 4 * ((2 * rg) ^ swz(d)));
        ulonglong2 xb = *reinterpret_cast<const ulonglong2*>(xp + 4 * ((2 * rg + 1) ^ swz(d)));
        float2 wk = *reinterpret_cast<const float2*>(&s->wc[d][64 + 2 * cg]);
        ull w0 = splat2(wk.x), w1 = splat2(wk.y);
        ffma2(ka[0][0], xa.x, w0); ffma2(ka[0][1], xa.x, w1);
        ffma2(ka[1][0], xa.y, w0); ffma2(ka[1][1], xa.y, w1);
        ffma2(ka[2][0], xb.x, w0); ffma2(ka[2][1], xb.x, w1);
        ffma2(ka[3][0], xb.y, w0); ffma2(ka[3][1], xb.y, w1);
    }
    __syncthreads();   // all xg reads done; safe to overwrite with G

    // gate epilogue: G = sigmoid(P + bg) -> xg (same transposed+swizzled layout)
    #pragma unroll
    for (int c = 0; c < 8; ++c) {
        int col = 8 * cg + c;
        float bgc = s->bgv[col];
        float g[8];
        #pragma unroll
        for (int r = 0; r < 8; ++r) {
            float lo, hi;
            unpack2(ga[r][c >> 1], lo, hi);
            float v = (c & 1) ? hi : lo;
            g[r] = sigmoid_fast(v + bgc);
        }
        float* dst = &s->xg[col * NSEQ];
        *reinterpret_cast<float4*>(dst + 4 * ((2 * rg) ^ swz(col)))     = make_float4(g[0], g[1], g[2], g[3]);
        *reinterpret_cast<float4*>(dst + 4 * ((2 * rg + 1) ^ swz(col))) = make_float4(g[4], g[5], g[6], g[7]);
    }
    // kv epilogue
    if (cg < 4) {
        #pragma unroll
        for (int p = 0; p < 4; ++p) {
            float a0, a1, b0, b1;
            unpack2(ka[p][0], a0, a1);   // col 2cg, rows 2p,2p+1
            unpack2(ka[p][1], b0, b1);   // col 2cg+1
            s->kbuf[8 * rg + 2 * p    ][2 * cg]     = a0;
            s->kbuf[8 * rg + 2 * p    ][2 * cg + 1] = b0;
            s->kbuf[8 * rg + 2 * p + 1][2 * cg]     = a1;
            s->kbuf[8 * rg + 2 * p + 1][2 * cg + 1] = b1;
        }
    } else {
        int c0 = 2 * cg - 8;
        float a[8], b[8];
        #pragma unroll
        for (int p = 0; p < 4; ++p) {
            unpack2(ka[p][0], a[2 * p], a[2 * p + 1]);
            unpack2(ka[p][1], b[2 * p], b[2 * p + 1]);
        }
        *reinterpret_cast<float4*>(&s->vT[c0 * NSEQ + 8 * rg])           = make_float4(a[0], a[1], a[2], a[3]);
        *reinterpret_cast<float4*>(&s->vT[c0 * NSEQ + 8 * rg + 4])       = make_float4(a[4], a[5], a[6], a[7]);
        *reinterpret_cast<float4*>(&s->vT[(c0 + 1) * NSEQ + 8 * rg])     = make_float4(b[0], b[1], b[2], b[3]);
        *reinterpret_cast<float4*>(&s->vT[(c0 + 1) * NSEQ + 8 * rg + 4]) = make_float4(b[4], b[5], b[6], b[7]);
    }
    // qvec partials (xsum was written before the previous barrier)
    {
        int dg = tid >> 6, c = tid & 63;
        float p = 0.f;
        #pragma unroll
        for (int i = 0; i < 8; ++i) p = fmaf(s->xsum[8 * dg + i], wqr[i], p);
        s->xpart[dg][c] = p;
    }
    __syncthreads();

    if (tid < 64) {
        float q = 0.f;
        #pragma unroll
        for (int dg = 0; dg < 8; ++dg) q += s->xpart[dg][tid];
        s->qvec[tid] = q * (float)(0.35355339059327373 / 512.0); // (1/sqrt(8))/N
    }
    __syncthreads();

    // ---------------- scores[h][n] ----------------
    {
        float4 k0 = *reinterpret_cast<const float4*>(&s->kbuf[tid][0]);
        float4 k1 = *reinterpret_cast<const float4*>(&s->kbuf[tid][4]);
        #pragma unroll
        for (int h = 0; h < 8; ++h) {
            const float* qf = &s->qvec[h * 8];
            float sc = qf[0]*k0.x + qf[1]*k0.y + qf[2]*k0.z + qf[3]*k0.w
                     + qf[4]*k1.x + qf[5]*k1.y + qf[6]*k1.z + qf[7]*k1.w;
            s->scores[h * NSEQ + tid] = sc;
        }
    }
    __syncthreads();

    // ---------------- softmax + o = attn @ v (one warp per head) ----------------
    if (wid < 8) {
        float sv[16];
        float m = -1e30f;
        #pragma unroll
        for (int k = 0; k < 16; ++k) {
            sv[k] = s->scores[wid * NSEQ + lane + 32 * k];
            m = fmaxf(m, sv[k]);
        }
        #pragma unroll
        for (int off = 16; off > 0; off >>= 1)
            m = fmaxf(m, __shfl_xor_sync(0xffffffffu, m, off));
        float ssum = 0.f;
        float acc[8];
        #pragma unroll
        for (int d = 0; d < 8; ++d) acc[d] = 0.f;
        #pragma unroll
        for (int k = 0; k < 16; ++k) {
            float e = __expf(sv[k] - m);
            ssum += e;
            int n = lane + 32 * k;
            #pragma unroll
            for (int d = 0; d < 8; ++d)
                acc[d] = fmaf(e, s->vT[d * NSEQ + n], acc[d]);
        }
        #pragma unroll
        for (int off = 16; off > 0; off >>= 1) {
            ssum += __shfl_xor_sync(0xffffffffu, ssum, off);
            #pragma unroll
            for (int d = 0; d < 8; ++d)
                acc[d] += __shfl_xor_sync(0xffffffffu, acc[d], off);
        }
        if (lane == 0) {
            float inv = 1.f / ssum;
            #pragma unroll
            for (int d = 0; d < 8; ++d) s->ovec[wid * 8 + d] = acc[d] * inv;
        }
    }
    __syncthreads();

    // fold ovec into Wo rows
    #pragma unroll
    for (int i = 0; i < 8; ++i) {
        int idx = tid + i * NT;
        s->wo[idx] *= s->ovec[idx >> 6];
    }
    __syncthreads();

    // ---------------- pass B: out = G @ Wo' + bo ----------------
    {
        ull acc[8][4];
        #pragma unroll
        for (int i = 0; i < 8; ++i)
            #pragma unroll
            for (int p = 0; p < 4; ++p) acc[i][p] = 0;

        #pragma unroll 4
        for (int d = 0; d < 64; ++d) {
            const float* gp = &s->xg[d * NSEQ];
            float4 xa = *reinterpret_cast<const float4*>(gp + 4 * ((2 * rg) ^ swz(d)));
            float4 xb = *reinterpret_cast<const float4*>(gp + 4 * ((2 * rg + 1) ^ swz(d)));
            ulonglong2 wA = *reinterpret_cast<const ulonglong2*>(&s->wo[d * 64 + 8 * cg]);
            ulonglong2 wB = *reinterpret_cast<const ulonglong2*>(&s->wo[d * 64 + 8 * cg + 4]);
            ull t;
            t = splat2(xa.x); ffma2(acc[0][0],t,wA.x); ffma2(acc[0][1],t,wA.y); ffma2(acc[0][2],t,wB.x); ffma2(acc[0][3],t,wB.y);
            t = splat2(xa.y); ffma2(acc[1][0],t,wA.x); ffma2(acc[1][1],t,wA.y); ffma2(acc[1][2],t,wB.x); ffma2(acc[1][3],t,wB.y);
            t = splat2(xa.z); ffma2(acc[2][0],t,wA.x); ffma2(acc[2][1],t,wA.y); ffma2(acc[2][2],t,wB.x); ffma2(acc[2][3],t,wB.y);
            t = splat2(xa.w); ffma2(acc[3][0],t,wA.x); ffma2(acc[3][1],t,wA.y); ffma2(acc[3][2],t,wB.x); ffma2(acc[3][3],t,wB.y);
            t = splat2(xb.x); ffma2(acc[4][0],t,wA.x); ffma2(acc[4][1],t,wA.y); ffma2(acc[4][2],t,wB.x); ffma2(acc[4][3],t,wB.y);
            t = splat2(xb.y); ffma2(acc[5][0],t,wA.x); ffma2(acc[5][1],t,wA.y); ffma2(acc[5][2],t,wB.x); ffma2(acc[5][3],t,wB.y);
            t = splat2(xb.z); ffma2(acc[6][0],t,wA.x); ffma2(acc[6][1],t,wA.y); ffma2(acc[6][2],t,wB.x); ffma2(acc[6][3],t,wB.y);
            t = splat2(xb.w); ffma2(acc[7][0],t,wA.x); ffma2(acc[7][1],t,wA.y); ffma2(acc[7][2],t,wB.x); ffma2(acc[7][3],t,wB.y);
        }

        const ulonglong2 boA = *reinterpret_cast<const ulonglong2*>(&s->bov[8 * cg]);
        const ulonglong2 boB = *reinterpret_cast<const ulonglong2*>(&s->bov[8 * cg + 4]);
        #pragma unroll
        for (int i = 0; i < 8; ++i) {
            size_t row = (size_t)(8 * rg + i);
            float* op = out + (row * LRES + l) * 64 + 8 * cg;
            ulonglong2 v0, v1;
            v0.x = add2(acc[i][0], boA.x); v0.y = add2(acc[i][1], boA.y);
            v1.x = add2(acc[i][2], boB.x); v1.y = add2(acc[i][3], boB.y);
            *reinterpret_cast<ulonglong2*>(op)     = v0;
            *reinterpret_cast<ulonglong2*>(op + 4) = v1;
        }
    }
}

extern "C" void kernel_launch(void* const* d_in, const int* in_sizes, int n_in,
                              void* d_out, int out_size) {
    const float* msa = (const float*)d_in[0];
    const float* lnw = (const float*)d_in[1];
    const float* lnb = (const float*)d_in[2];
    const float* wq  = (const float*)d_in[3];
    const float* wk  = (const float*)d_in[4];
    const float* wv  = (const float*)d_in[5];
    const float* wg  = (const float*)d_in[6];
    const float* bg  = (const float*)d_in[7];
    const float* wo  = (const float*)d_in[8];
    const float* bo  = (const float*)d_in[9];
    float* out = (float*)d_out;

    const int smem_bytes = (int)sizeof(Smem);
    cudaFuncSetAttribute(msa_col_attn_v5,
                         cudaFuncAttributeMaxDynamicSharedMemorySize, smem_bytes);
    msa_col_attn_v5<<<LRES, NT, smem_bytes>>>(
        msa, lnw, lnb, wq, wk, wv, wg, bg, wo, bo, out);
}